// round 9
// baseline (speedup 1.0000x reference)
#include <cuda_runtime.h>
#include <cuda_bf16.h>

// GraphSAGE 2-layer, N=100000, E=1600000, D=128.
// R9: aggregation FUSED into the persistent GEMM — staging threads compute
// neighbor-mean slices on the fly (chunks 0-3) and load the node's own row
// (chunks 4-7). g_mean round-trip and the agg kernels are eliminated.

#define N_NODES 100000
#define N_EDGES 1600000
#define DFEAT   128
#define SCAN_BLK 1024
#define MAX_SCAN_BLOCKS ((N_NODES + SCAN_BLK - 1) / SCAN_BLK + 1)

// ---------------- scratch (device globals; no allocation allowed) ----------
__device__ int   g_is_i64;
__device__ int   g_src[N_EDGES];
__device__ int   g_dst[N_EDGES];
__device__ int   g_cursor[N_NODES];
__device__ int   g_rowptr[N_NODES + 1];
__device__ int   g_col[N_EDGES];
__device__ int   g_bsum[MAX_SCAN_BLOCKS];
__device__ float g_h[(size_t)N_NODES * DFEAT];

// ---------------- small helpers -------------------------------------------
__device__ __forceinline__ unsigned long long dup_f32x2(float a) {
    unsigned long long r;
    asm("mov.b64 %0, {%1, %1};" : "=l"(r) : "f"(a));
    return r;
}
__device__ __forceinline__ void unpack_f32x2(unsigned long long v, float& lo, float& hi) {
    asm("mov.b64 {%0, %1}, %2;" : "=f"(lo), "=f"(hi) : "l"(v));
}
#define FFMA2(d, a, b, c) \
    asm("fma.rn.f32x2 %0, %1, %2, %3;" : "=l"(d) : "l"(a), "l"(b), "l"(c))

__device__ __forceinline__ int clamp_node(int v, int n) {
    unsigned u = (unsigned)v;
    return (u < (unsigned)n) ? v : 0;
}

// ---------------- edge dtype detect + (extract + degree count) -------------
__global__ void detect_kernel(const int* __restrict__ ew) {
    int flag = 0;
    for (int i = 1; i < 128; i += 2) flag |= ew[i];
    g_is_i64 = (flag == 0) ? 1 : 0;
}

__global__ void convert_count_kernel(const int* __restrict__ ew, int nedges, int nnodes) {
    int e = blockIdx.x * blockDim.x + threadIdx.x;
    if (e >= nedges) return;
    int s, d;
    if (g_is_i64) {
        s = ew[2 * (size_t)e];
        d = ew[2 * ((size_t)nedges + e)];
    } else {
        s = ew[e];
        d = ew[(size_t)nedges + e];
    }
    s = clamp_node(s, nnodes);
    d = clamp_node(d, nnodes);
    g_src[e] = s;
    g_dst[e] = d;
    atomicAdd(&g_cursor[d], 1);
}

__global__ void zero_int_kernel(int* p, int n) {
    int i = blockIdx.x * blockDim.x + threadIdx.x;
    if (i < n) p[i] = 0;
}

// ---------------- parallel scan: 3 phases ----------------------------------
__global__ void __launch_bounds__(SCAN_BLK)
scan_partial_kernel(int n) {
    __shared__ int warp_sums[32];
    int i = blockIdx.x * SCAN_BLK + threadIdx.x;
    int lane = threadIdx.x & 31;
    int wid = threadIdx.x >> 5;
    int v = (i < n) ? g_cursor[i] : 0;
    int x = v;
#pragma unroll
    for (int o = 1; o < 32; o <<= 1) {
        int y = __shfl_up_sync(0xffffffffu, x, o);
        if (lane >= o) x += y;
    }
    if (lane == 31) warp_sums[wid] = x;
    __syncthreads();
    if (wid == 0) {
        int s = warp_sums[lane];
#pragma unroll
        for (int o = 1; o < 32; o <<= 1) {
            int y = __shfl_up_sync(0xffffffffu, s, o);
            if (lane >= o) s += y;
        }
        warp_sums[lane] = s;
    }
    __syncthreads();
    int base = (wid > 0) ? warp_sums[wid - 1] : 0;
    if (i < n) g_rowptr[i] = base + x - v;
    if (threadIdx.x == SCAN_BLK - 1) g_bsum[blockIdx.x] = base + x;
}

__global__ void __launch_bounds__(SCAN_BLK)
scan_bsums_kernel(int nblocks, int n) {
    __shared__ int warp_sums[32];
    int t = threadIdx.x;
    int lane = t & 31;
    int wid = t >> 5;
    int v = (t < nblocks) ? g_bsum[t] : 0;
    int x = v;
#pragma unroll
    for (int o = 1; o < 32; o <<= 1) {
        int y = __shfl_up_sync(0xffffffffu, x, o);
        if (lane >= o) x += y;
    }
    if (lane == 31) warp_sums[wid] = x;
    __syncthreads();
    if (wid == 0) {
        int s = warp_sums[lane];
#pragma unroll
        for (int o = 1; o < 32; o <<= 1) {
            int y = __shfl_up_sync(0xffffffffu, s, o);
            if (lane >= o) s += y;
        }
        warp_sums[lane] = s;
    }
    __syncthreads();
    int base = (wid > 0) ? warp_sums[wid - 1] : 0;
    if (t < nblocks) g_bsum[t] = base + x - v;
    if (t == SCAN_BLK - 1) g_rowptr[n] = base + x;
}

__global__ void __launch_bounds__(SCAN_BLK)
scan_add_kernel(int n) {
    int i = blockIdx.x * SCAN_BLK + threadIdx.x;
    if (i >= n) return;
    g_rowptr[i] += g_bsum[blockIdx.x];
    g_cursor[i] = 0;
}

__global__ void fill_csr_kernel(int nedges) {
    int e = blockIdx.x * blockDim.x + threadIdx.x;
    if (e >= nedges) return;
    int dst = g_dst[e];
    int pos = g_rowptr[dst] + atomicAdd(&g_cursor[dst], 1);
    g_col[pos] = g_src[e];
}

// ---------------- fused persistent SAGE layer -------------------------------
// out[n][j] = sum_k mean_nb(feat)[n][k]*Wl[j][k] + sum_k feat[n][k]*Wr[j][k] + b[j]
// grid=148 persistent CTAs x 512 threads; weights resident; 128-node tiles.
// Staging thread (node = tid>>2, q = tid&3) produces an 8-k slice per chunk:
//   chunks 0-3: gather-mean over neighbors (CSR) of feat slice
//   chunks 4-7: node's own feat slice
// then writes it duplicated as (a,a) f32x2 into the double-buffered sA2.
// Compute per k: 8x LDS.64 broadcast + 1x LDS.128 + 16x FFMA2 (fma-bound).
#define W_STRIDE 132
#define GTILE    128
#define GEMM_SMEM (256 * W_STRIDE * 4 + 2 * 32 * 128 * 8)

__global__ void __launch_bounds__(512)
sage_fused_kernel(const float* __restrict__ feat,
                  const float* __restrict__ Wl,
                  const float* __restrict__ Wr,
                  const float* __restrict__ bias,
                  float* __restrict__ out,
                  int nnodes, int relu, int ntiles) {
    extern __shared__ float smem[];
    float* sW = smem;                                                   // 256*132
    unsigned long long* sA2 =
        reinterpret_cast<unsigned long long*>(smem + 256 * W_STRIDE);   // 2*32*128

    int tid = threadIdx.x;
    // Load + transpose weights ONCE per CTA.
    for (int idx = tid; idx < 128 * 128; idx += 512) {
        int j = idx >> 7;
        int k = idx & 127;
        sW[k * W_STRIDE + j] = Wl[idx];
        sW[(k + 128) * W_STRIDE + j] = Wr[idx];
    }

    int lane = tid & 31;
    int warp = tid >> 5;
    int j0 = lane * 4;

    int st_node = tid >> 2;           // 0..127 node within tile
    int st_q = tid & 3;               // 0..3 -> k offsets q*8..q*8+7
    int kb = st_q * 8;

    // bias packed once
    float4 bv = *reinterpret_cast<const float4*>(bias + j0);
    unsigned long long b01, b23;
    asm("mov.b64 %0, {%1, %2};" : "=l"(b01) : "f"(bv.x), "f"(bv.y));
    asm("mov.b64 %0, {%1, %2};" : "=l"(b23) : "f"(bv.z), "f"(bv.w));

    for (int tile = blockIdx.x; tile < ntiles; tile += gridDim.x) {
        int base_node = tile * GTILE;
        int gnode = base_node + st_node;
        if (gnode >= nnodes) gnode = nnodes - 1;

        int start = g_rowptr[gnode];
        int end = g_rowptr[gnode + 1];
        float inv = 1.f / fmaxf((float)(end - start), 1.f);
        const float* self_row = feat + (size_t)gnode * DFEAT + kb;

        unsigned long long acc[16];
#pragma unroll
        for (int m = 0; m < 8; ++m) { acc[2 * m] = b01; acc[2 * m + 1] = b23; }

        for (int c = 0; c < 8; ++c) {
            float4 v0, v1;
            if (c < 4) {
                // gather-mean of neighbor feat slices (k = c*32 + kb .. +7)
                int koff = c * 32 + kb;
                float4 s0 = {0.f, 0.f, 0.f, 0.f};
                float4 s1 = {0.f, 0.f, 0.f, 0.f};
                int p = start;
                for (; p + 2 <= end; p += 2) {
                    int n0 = g_col[p];
                    int n1 = g_col[p + 1];
                    const float4* r0 = reinterpret_cast<const float4*>(
                        feat + (size_t)n0 * DFEAT + koff);
                    const float4* r1 = reinterpret_cast<const float4*>(
                        feat + (size_t)n1 * DFEAT + koff);
                    float4 a0 = r0[0], a1 = r0[1];
                    float4 c0 = r1[0], c1 = r1[1];
                    s0.x += a0.x + c0.x; s0.y += a0.y + c0.y;
                    s0.z += a0.z + c0.z; s0.w += a0.w + c0.w;
                    s1.x += a1.x + c1.x; s1.y += a1.y + c1.y;
                    s1.z += a1.z + c1.z; s1.w += a1.w + c1.w;
                }
                if (p < end) {
                    int n0 = g_col[p];
                    const float4* r0 = reinterpret_cast<const float4*>(
                        feat + (size_t)n0 * DFEAT + koff);
                    float4 a0 = r0[0], a1 = r0[1];
                    s0.x += a0.x; s0.y += a0.y; s0.z += a0.z; s0.w += a0.w;
                    s1.x += a1.x; s1.y += a1.y; s1.z += a1.z; s1.w += a1.w;
                }
                v0.x = s0.x * inv; v0.y = s0.y * inv; v0.z = s0.z * inv; v0.w = s0.w * inv;
                v1.x = s1.x * inv; v1.y = s1.y * inv; v1.z = s1.z * inv; v1.w = s1.w * inv;
            } else {
                const float4* r = reinterpret_cast<const float4*>(
                    self_row + (c - 4) * 32);
                v0 = r[0];
                v1 = r[1];
            }

            unsigned long long* buf = sA2 + (c & 1) * (32 * 128);
            buf[(kb + 0) * 128 + st_node] = dup_f32x2(v0.x);
            buf[(kb + 1) * 128 + st_node] = dup_f32x2(v0.y);
            buf[(kb + 2) * 128 + st_node] = dup_f32x2(v0.z);
            buf[(kb + 3) * 128 + st_node] = dup_f32x2(v0.w);
            buf[(kb + 4) * 128 + st_node] = dup_f32x2(v1.x);
            buf[(kb + 5) * 128 + st_node] = dup_f32x2(v1.y);
            buf[(kb + 6) * 128 + st_node] = dup_f32x2(v1.z);
            buf[(kb + 7) * 128 + st_node] = dup_f32x2(v1.w);
            __syncthreads();   // buffer c ready; buffer c-2 consumers done

            int krow = c * 32;
            const unsigned long long* aw_base = buf + warp * 8;
#pragma unroll 4
            for (int kk = 0; kk < 32; ++kk) {
                ulonglong2 wv = *reinterpret_cast<const ulonglong2*>(
                    &sW[(krow + kk) * W_STRIDE + j0]);
                const unsigned long long* ar = aw_base + kk * 128;
#pragma unroll
                for (int m = 0; m < 8; ++m) {
                    unsigned long long aa = ar[m];   // LDS.64 broadcast
                    FFMA2(acc[2 * m], aa, wv.x, acc[2 * m]);
                    FFMA2(acc[2 * m + 1], aa, wv.y, acc[2 * m + 1]);
                }
            }
        }

        int wnode = base_node + warp * 8;
#pragma unroll
        for (int m = 0; m < 8; ++m) {
            int nd = wnode + m;
            if (nd >= nnodes) break;
            float4 o;
            unpack_f32x2(acc[2 * m], o.x, o.y);
            unpack_f32x2(acc[2 * m + 1], o.z, o.w);
            if (relu) {
                o.x = fmaxf(o.x, 0.f); o.y = fmaxf(o.y, 0.f);
                o.z = fmaxf(o.z, 0.f); o.w = fmaxf(o.w, 0.f);
            }
            *reinterpret_cast<float4*>(out + (size_t)nd * DFEAT + j0) = o;
        }
        // no end-of-tile barrier needed: next staging writes buf0 while the
        // slowest warps can only still be reading buf1 (chunk 7).
    }
}

// ---------------- launch ----------------------------------------------------
extern "C" void kernel_launch(void* const* d_in, const int* in_sizes, int n_in,
                              void* d_out, int out_size) {
    const float* x   = (const float*)d_in[0];
    const int*   ew  = (const int*)d_in[1];
    const float* Wl1 = (const float*)d_in[2];
    const float* bl1 = (const float*)d_in[3];
    const float* Wr1 = (const float*)d_in[4];
    const float* Wl2 = (const float*)d_in[5];
    const float* bl2 = (const float*)d_in[6];
    const float* Wr2 = (const float*)d_in[7];
    float*       out = (float*)d_out;

    int n = in_sizes[0] / DFEAT;      // 100000
    int e = in_sizes[1] / 2;          // 1600000

    void *p_h_v, *p_cursor_v;
    cudaGetSymbolAddress(&p_h_v, g_h);
    cudaGetSymbolAddress(&p_cursor_v, g_cursor);
    float* p_h = (float*)p_h_v;
    int* p_cursor = (int*)p_cursor_v;

    cudaFuncSetAttribute(sage_fused_kernel,
                         cudaFuncAttributeMaxDynamicSharedMemorySize, GEMM_SMEM);

    int zb = (n + 255) / 256;
    int eb = (e + 255) / 256;
    int sb = (n + SCAN_BLK - 1) / SCAN_BLK;
    int ntiles = (n + GTILE - 1) / GTILE;

    // ---- edge extraction + degree count ----
    detect_kernel<<<1, 1>>>(ew);
    zero_int_kernel<<<zb, 256>>>(p_cursor, n);
    convert_count_kernel<<<eb, 256>>>(ew, e, n);

    // ---- parallel scan (3 phases) ----
    scan_partial_kernel<<<sb, SCAN_BLK>>>(n);
    scan_bsums_kernel<<<1, SCAN_BLK>>>(sb, n);
    scan_add_kernel<<<sb, SCAN_BLK>>>(n);

    fill_csr_kernel<<<eb, 256>>>(e);

    // ---- layer 1 (fused agg + GEMM) ----
    sage_fused_kernel<<<148, 512, GEMM_SMEM>>>(x, Wl1, Wr1, bl1, p_h, n, 1, ntiles);

    // ---- layer 2 (fused agg + GEMM) ----
    sage_fused_kernel<<<148, 512, GEMM_SMEM>>>(p_h, Wl2, Wr2, bl2, out, n, 0, ntiles);
}

// round 10
// speedup vs baseline: 1.5900x; 1.5900x over previous
#include <cuda_runtime.h>
#include <cuda_bf16.h>

// GraphSAGE 2-layer, N=100000, E=1600000, D=128.
// R10: R8 (best, 598.8us) + GEMM inner-loop A-broadcast via 4x uniform
// LDS.128 instead of 8x LDS.64 — smem wavefronts per warp-k drop 12 -> 8,
// matching the fma-pipe budget. Fusion (R9) reverted: per-thread divergent
// gather was the regression cause.

#define N_NODES 100000
#define N_EDGES 1600000
#define DFEAT   128
#define SCAN_BLK 1024
#define MAX_SCAN_BLOCKS ((N_NODES + SCAN_BLK - 1) / SCAN_BLK + 1)

// ---------------- scratch (device globals; no allocation allowed) ----------
__device__ int   g_is_i64;
__device__ int   g_src[N_EDGES];
__device__ int   g_dst[N_EDGES];
__device__ int   g_cursor[N_NODES];
__device__ int   g_rowptr[N_NODES + 1];
__device__ int   g_col[N_EDGES];
__device__ int   g_bsum[MAX_SCAN_BLOCKS];
__device__ float g_mean[(size_t)N_NODES * DFEAT];
__device__ float g_h[(size_t)N_NODES * DFEAT];

// ---------------- small helpers -------------------------------------------
__device__ __forceinline__ unsigned long long dup_f32x2(float a) {
    unsigned long long r;
    asm("mov.b64 %0, {%1, %1};" : "=l"(r) : "f"(a));
    return r;
}
__device__ __forceinline__ void unpack_f32x2(unsigned long long v, float& lo, float& hi) {
    asm("mov.b64 {%0, %1}, %2;" : "=f"(lo), "=f"(hi) : "l"(v));
}
#define FFMA2(d, a, b, c) \
    asm("fma.rn.f32x2 %0, %1, %2, %3;" : "=l"(d) : "l"(a), "l"(b), "l"(c))

__device__ __forceinline__ int clamp_node(int v, int n) {
    unsigned u = (unsigned)v;
    return (u < (unsigned)n) ? v : 0;
}

// ---------------- edge dtype detect + (extract + degree count) -------------
__global__ void detect_kernel(const int* __restrict__ ew) {
    int flag = 0;
    for (int i = 1; i < 128; i += 2) flag |= ew[i];
    g_is_i64 = (flag == 0) ? 1 : 0;
}

__global__ void convert_count_kernel(const int* __restrict__ ew, int nedges, int nnodes) {
    int e = blockIdx.x * blockDim.x + threadIdx.x;
    if (e >= nedges) return;
    int s, d;
    if (g_is_i64) {
        s = ew[2 * (size_t)e];
        d = ew[2 * ((size_t)nedges + e)];
    } else {
        s = ew[e];
        d = ew[(size_t)nedges + e];
    }
    s = clamp_node(s, nnodes);
    d = clamp_node(d, nnodes);
    g_src[e] = s;
    g_dst[e] = d;
    atomicAdd(&g_cursor[d], 1);
}

__global__ void zero_int_kernel(int* p, int n) {
    int i = blockIdx.x * blockDim.x + threadIdx.x;
    if (i < n) p[i] = 0;
}

// ---------------- parallel scan: 3 phases ----------------------------------
__global__ void __launch_bounds__(SCAN_BLK)
scan_partial_kernel(int n) {
    __shared__ int warp_sums[32];
    int i = blockIdx.x * SCAN_BLK + threadIdx.x;
    int lane = threadIdx.x & 31;
    int wid = threadIdx.x >> 5;
    int v = (i < n) ? g_cursor[i] : 0;
    int x = v;
#pragma unroll
    for (int o = 1; o < 32; o <<= 1) {
        int y = __shfl_up_sync(0xffffffffu, x, o);
        if (lane >= o) x += y;
    }
    if (lane == 31) warp_sums[wid] = x;
    __syncthreads();
    if (wid == 0) {
        int s = warp_sums[lane];
#pragma unroll
        for (int o = 1; o < 32; o <<= 1) {
            int y = __shfl_up_sync(0xffffffffu, s, o);
            if (lane >= o) s += y;
        }
        warp_sums[lane] = s;
    }
    __syncthreads();
    int base = (wid > 0) ? warp_sums[wid - 1] : 0;
    if (i < n) g_rowptr[i] = base + x - v;
    if (threadIdx.x == SCAN_BLK - 1) g_bsum[blockIdx.x] = base + x;
}

__global__ void __launch_bounds__(SCAN_BLK)
scan_bsums_kernel(int nblocks, int n) {
    __shared__ int warp_sums[32];
    int t = threadIdx.x;
    int lane = t & 31;
    int wid = t >> 5;
    int v = (t < nblocks) ? g_bsum[t] : 0;
    int x = v;
#pragma unroll
    for (int o = 1; o < 32; o <<= 1) {
        int y = __shfl_up_sync(0xffffffffu, x, o);
        if (lane >= o) x += y;
    }
    if (lane == 31) warp_sums[wid] = x;
    __syncthreads();
    if (wid == 0) {
        int s = warp_sums[lane];
#pragma unroll
        for (int o = 1; o < 32; o <<= 1) {
            int y = __shfl_up_sync(0xffffffffu, s, o);
            if (lane >= o) s += y;
        }
        warp_sums[lane] = s;
    }
    __syncthreads();
    int base = (wid > 0) ? warp_sums[wid - 1] : 0;
    if (t < nblocks) g_bsum[t] = base + x - v;
    if (t == SCAN_BLK - 1) g_rowptr[n] = base + x;
}

__global__ void __launch_bounds__(SCAN_BLK)
scan_add_kernel(int n) {
    int i = blockIdx.x * SCAN_BLK + threadIdx.x;
    if (i >= n) return;
    g_rowptr[i] += g_bsum[blockIdx.x];
    g_cursor[i] = 0;
}

__global__ void fill_csr_kernel(int nedges) {
    int e = blockIdx.x * blockDim.x + threadIdx.x;
    if (e >= nedges) return;
    int dst = g_dst[e];
    int pos = g_rowptr[dst] + atomicAdd(&g_cursor[dst], 1);
    g_col[pos] = g_src[e];
}

// ---------------- mean aggregation: one warp per node ----------------------
__global__ void agg_mean_kernel(const float* __restrict__ feat, int nnodes) {
    int gwarp = (blockIdx.x * blockDim.x + threadIdx.x) >> 5;
    int lane = threadIdx.x & 31;
    if (gwarp >= nnodes) return;

    int start = g_rowptr[gwarp];
    int end = g_rowptr[gwarp + 1];
    float ax = 0.f, ay = 0.f, az = 0.f, aw = 0.f;
    int lane4 = lane * 4;

    for (int base = start; base < end; base += 32) {
        int m = min(32, end - base);
        int sv = (lane < m) ? g_col[base + lane] : 0;
        int kk = 0;
        for (; kk + 4 <= m; kk += 4) {
            int s0 = __shfl_sync(0xffffffffu, sv, kk);
            int s1 = __shfl_sync(0xffffffffu, sv, kk + 1);
            int s2 = __shfl_sync(0xffffffffu, sv, kk + 2);
            int s3 = __shfl_sync(0xffffffffu, sv, kk + 3);
            float4 v0 = *reinterpret_cast<const float4*>(feat + (size_t)s0 * DFEAT + lane4);
            float4 v1 = *reinterpret_cast<const float4*>(feat + (size_t)s1 * DFEAT + lane4);
            float4 v2 = *reinterpret_cast<const float4*>(feat + (size_t)s2 * DFEAT + lane4);
            float4 v3 = *reinterpret_cast<const float4*>(feat + (size_t)s3 * DFEAT + lane4);
            ax += v0.x + v1.x + v2.x + v3.x;
            ay += v0.y + v1.y + v2.y + v3.y;
            az += v0.z + v1.z + v2.z + v3.z;
            aw += v0.w + v1.w + v2.w + v3.w;
        }
        for (; kk < m; ++kk) {
            int s = __shfl_sync(0xffffffffu, sv, kk);
            float4 v = *reinterpret_cast<const float4*>(feat + (size_t)s * DFEAT + lane4);
            ax += v.x; ay += v.y; az += v.z; aw += v.w;
        }
    }
    float inv = 1.f / fmaxf((float)(end - start), 1.f);
    float4 o;
    o.x = ax * inv; o.y = ay * inv; o.z = az * inv; o.w = aw * inv;
    *reinterpret_cast<float4*>(g_mean + (size_t)gwarp * DFEAT + lane4) = o;
}

// ---------------- persistent fused SAGE GEMM (128-node tiles) ---------------
// out[n][j] = sum_k mean[n][k]*Wl[j][k] + sum_k feat[n][k]*Wr[j][k] + b[j]
// grid=148 persistent CTAs x 512 threads; weights loaded once per CTA;
// loop over 128-node tiles; 8 nodes/warp; double-buffered dup-A staging.
// Inner loop per k: 4x uniform LDS.128 (A dup-pairs, broadcast) +
// 1x LDS.128 (W) + 16x FFMA2 -> 8 smem wavefronts per warp-k (balanced).
#define W_STRIDE 132
#define GTILE    128
#define GEMM_SMEM (256 * W_STRIDE * 4 + 2 * 32 * 128 * 8)

__global__ void __launch_bounds__(512)
sage_gemm_kernel(const float* __restrict__ A0,   // mean  (k = 0..127)
                 const float* __restrict__ A1,   // feat  (k = 128..255)
                 const float* __restrict__ Wl,
                 const float* __restrict__ Wr,
                 const float* __restrict__ bias,
                 float* __restrict__ out,
                 int nnodes, int relu, int ntiles) {
    extern __shared__ float smem[];
    float* sW = smem;                                                   // 256*132
    unsigned long long* sA2 =
        reinterpret_cast<unsigned long long*>(smem + 256 * W_STRIDE);   // 2*32*128

    int tid = threadIdx.x;
    // Load + transpose weights ONCE per CTA.
    for (int idx = tid; idx < 128 * 128; idx += 512) {
        int j = idx >> 7;
        int k = idx & 127;
        sW[k * W_STRIDE + j] = Wl[idx];
        sW[(k + 128) * W_STRIDE + j] = Wr[idx];
    }

    int lane = tid & 31;
    int warp = tid >> 5;
    int j0 = lane * 4;

    // staging role: thread loads 8 k-values (two float4) of one node per chunk
    int st_node = tid >> 2;           // 0..127
    int st_q = tid & 3;               // 0..3 -> k offsets q*8..q*8+7
    int kb = st_q * 8;

    // bias packed once
    float4 bv = *reinterpret_cast<const float4*>(bias + j0);
    unsigned long long b01, b23;
    asm("mov.b64 %0, {%1, %2};" : "=l"(b01) : "f"(bv.x), "f"(bv.y));
    asm("mov.b64 %0, {%1, %2};" : "=l"(b23) : "f"(bv.z), "f"(bv.w));

    for (int tile = blockIdx.x; tile < ntiles; tile += gridDim.x) {
        int base_node = tile * GTILE;
        int st_gnode = base_node + st_node;
        if (st_gnode >= nnodes) st_gnode = nnodes - 1;
        const float* a0p = A0 + (size_t)st_gnode * DFEAT + st_q * 8;
        const float* a1p = A1 + (size_t)st_gnode * DFEAT + st_q * 8;

        // prefetch chunk 0
        float4 v0 = *reinterpret_cast<const float4*>(a0p);
        float4 v1 = *reinterpret_cast<const float4*>(a0p + 4);

        unsigned long long acc[16];
#pragma unroll
        for (int m = 0; m < 8; ++m) { acc[2 * m] = b01; acc[2 * m + 1] = b23; }

        for (int c = 0; c < 8; ++c) {
            unsigned long long* buf = sA2 + (c & 1) * (32 * 128);
            buf[(kb + 0) * 128 + st_node] = dup_f32x2(v0.x);
            buf[(kb + 1) * 128 + st_node] = dup_f32x2(v0.y);
            buf[(kb + 2) * 128 + st_node] = dup_f32x2(v0.z);
            buf[(kb + 3) * 128 + st_node] = dup_f32x2(v0.w);
            buf[(kb + 4) * 128 + st_node] = dup_f32x2(v1.x);
            buf[(kb + 5) * 128 + st_node] = dup_f32x2(v1.y);
            buf[(kb + 6) * 128 + st_node] = dup_f32x2(v1.z);
            buf[(kb + 7) * 128 + st_node] = dup_f32x2(v1.w);

            if (c + 1 < 8) {
                int cn = c + 1;
                const float* ap = (cn < 4) ? a0p : a1p;
                int koff = (cn & 3) * 32;
                v0 = *reinterpret_cast<const float4*>(ap + koff);
                v1 = *reinterpret_cast<const float4*>(ap + koff + 4);
            }
            __syncthreads();

            int krow = c * 32;
            const unsigned long long* aw_base = buf + warp * 8;
#pragma unroll 4
            for (int kk = 0; kk < 32; ++kk) {
                ulonglong2 wv = *reinterpret_cast<const ulonglong2*>(
                    &sW[(krow + kk) * W_STRIDE + j0]);
                // 4 uniform LDS.128 broadcasts: 8 contiguous dup-pairs (8 nodes)
                const ulonglong2* ar2 =
                    reinterpret_cast<const ulonglong2*>(aw_base + kk * 128);
                ulonglong2 a01 = ar2[0];
                ulonglong2 a23 = ar2[1];
                ulonglong2 a45 = ar2[2];
                ulonglong2 a67 = ar2[3];
                FFMA2(acc[0],  a01.x, wv.x, acc[0]);
                FFMA2(acc[1],  a01.x, wv.y, acc[1]);
                FFMA2(acc[2],  a01.y, wv.x, acc[2]);
                FFMA2(acc[3],  a01.y, wv.y, acc[3]);
                FFMA2(acc[4],  a23.x, wv.x, acc[4]);
                FFMA2(acc[5],  a23.x, wv.y, acc[5]);
                FFMA2(acc[6],  a23.y, wv.x, acc[6]);
                FFMA2(acc[7],  a23.y, wv.y, acc[7]);
                FFMA2(acc[8],  a45.x, wv.x, acc[8]);
                FFMA2(acc[9],  a45.x, wv.y, acc[9]);
                FFMA2(acc[10], a45.y, wv.x, acc[10]);
                FFMA2(acc[11], a45.y, wv.y, acc[11]);
                FFMA2(acc[12], a67.x, wv.x, acc[12]);
                FFMA2(acc[13], a67.x, wv.y, acc[13]);
                FFMA2(acc[14], a67.y, wv.x, acc[14]);
                FFMA2(acc[15], a67.y, wv.y, acc[15]);
            }
        }

        int wnode = base_node + warp * 8;
#pragma unroll
        for (int m = 0; m < 8; ++m) {
            int nd = wnode + m;
            if (nd >= nnodes) break;
            float4 o;
            unpack_f32x2(acc[2 * m], o.x, o.y);
            unpack_f32x2(acc[2 * m + 1], o.z, o.w);
            if (relu) {
                o.x = fmaxf(o.x, 0.f); o.y = fmaxf(o.y, 0.f);
                o.z = fmaxf(o.z, 0.f); o.w = fmaxf(o.w, 0.f);
            }
            *reinterpret_cast<float4*>(out + (size_t)nd * DFEAT + j0) = o;
        }
        __syncthreads();   // tile done before next staging overwrites buffers
    }
}

// ---------------- launch ----------------------------------------------------
extern "C" void kernel_launch(void* const* d_in, const int* in_sizes, int n_in,
                              void* d_out, int out_size) {
    const float* x   = (const float*)d_in[0];
    const int*   ew  = (const int*)d_in[1];
    const float* Wl1 = (const float*)d_in[2];
    const float* bl1 = (const float*)d_in[3];
    const float* Wr1 = (const float*)d_in[4];
    const float* Wl2 = (const float*)d_in[5];
    const float* bl2 = (const float*)d_in[6];
    const float* Wr2 = (const float*)d_in[7];
    float*       out = (float*)d_out;

    int n = in_sizes[0] / DFEAT;      // 100000
    int e = in_sizes[1] / 2;          // 1600000

    void *p_mean_v, *p_h_v, *p_cursor_v;
    cudaGetSymbolAddress(&p_mean_v, g_mean);
    cudaGetSymbolAddress(&p_h_v, g_h);
    cudaGetSymbolAddress(&p_cursor_v, g_cursor);
    float* p_mean = (float*)p_mean_v;
    float* p_h = (float*)p_h_v;
    int* p_cursor = (int*)p_cursor_v;

    cudaFuncSetAttribute(sage_gemm_kernel,
                         cudaFuncAttributeMaxDynamicSharedMemorySize, GEMM_SMEM);

    int zb = (n + 255) / 256;
    int eb = (e + 255) / 256;
    int ab = (n + 7) / 8;
    int sb = (n + SCAN_BLK - 1) / SCAN_BLK;
    int ntiles = (n + GTILE - 1) / GTILE;

    // ---- edge extraction + degree count ----
    detect_kernel<<<1, 1>>>(ew);
    zero_int_kernel<<<zb, 256>>>(p_cursor, n);
    convert_count_kernel<<<eb, 256>>>(ew, e, n);

    // ---- parallel scan (3 phases) ----
    scan_partial_kernel<<<sb, SCAN_BLK>>>(n);
    scan_bsums_kernel<<<1, SCAN_BLK>>>(sb, n);
    scan_add_kernel<<<sb, SCAN_BLK>>>(n);

    fill_csr_kernel<<<eb, 256>>>(e);

    // ---- layer 1 ----
    agg_mean_kernel<<<ab, 256>>>(x, n);
    sage_gemm_kernel<<<148, 512, GEMM_SMEM>>>(p_mean, x, Wl1, Wr1, bl1, p_h, n, 1, ntiles);

    // ---- layer 2 ----
    agg_mean_kernel<<<ab, 256>>>(p_h, n);
    sage_gemm_kernel<<<148, 512, GEMM_SMEM>>>(p_mean, p_h, Wl2, Wr2, bl2, out, n, 0, ntiles);
}